// round 11
// baseline (speedup 1.0000x reference)
#include <cuda_runtime.h>
#include <cuda_bf16.h>
#include <cstdint>

// Problem constants
#define SEQ    4096
#define DK     128
#define PLANE  (SEQ * DK)      // 524288 floats per (b,h) plane
#define PLANE4 (PLANE / 4)     // 131072 float4s per plane
#define PPB    8               // planes per block = 4 pipelined pairs

// Fused kernel: out[...,s,d] = R[d,d,s] * x[...,s,d]
// One block = one 32-seq x 128-dim tile applied to PPB planes, processed as
// software-pipelined pairs: pair p+1's 8 loads are issued BEFORE pair p's
// stores, so the read side of HBM never drains while writes retire.
// Diag slice read straight from R into smem, then cached in registers.
// .cs on loads and stores (read-once/write-once stream; keeps diag in L2).
__global__ void __launch_bounds__(256) rope_diag_kernel(
        const float* __restrict__ R,
        const float4* __restrict__ x,
        float4* __restrict__ out) {
    // Padded to 132 floats/row: 16B-aligned rows -> conflict-free LDS.128
    __shared__ float diag[32][132];

    const unsigned s0     = blockIdx.x * 32;        // 128 s-tiles (fast axis)
    const unsigned plane0 = blockIdx.y * PPB;       // 16 plane-octets
    const unsigned tid    = threadIdx.x;
    const unsigned warp   = tid >> 5;
    const unsigned lane   = tid & 31;

    // diag[s][d] = R[d*(DK+1)*SEQ + s]; each row a coalesced 128B read.
    #pragma unroll
    for (int r = 0; r < 16; r++) {
        unsigned d = warp + r * 8;
        diag[lane][d] = __ldg(&R[(size_t)d * ((DK + 1) * SEQ) + s0 + lane]);
    }
    __syncthreads();

    const unsigned tileBase = blockIdx.x * 1024;    // float4 offset in plane

    // Pre-read this thread's 4 diag chunks once (16 regs, reused x8 planes)
    float4 dvv[4];
    #pragma unroll
    for (int k = 0; k < 4; k++) {
        unsigned idx = k * 256 + tid;               // 0..1023 within tile
        unsigned s   = idx >> 5;
        unsigned d4  = (idx & 31) * 4;
        dvv[k] = *reinterpret_cast<const float4*>(&diag[s][d4]);
    }

    // Double-buffered pipeline over 4 plane-pairs.
    float4 xv[2][2][4];                             // [buf][planeInPair][k]

    // Prologue: load pair 0 into buf 0.
    #pragma unroll
    for (int p = 0; p < 2; p++) {
        const float4* xp = x + (size_t)(plane0 + p) * PLANE4 + tileBase;
        #pragma unroll
        for (int k = 0; k < 4; k++)
            xv[0][p][k] = __ldcs(&xp[k * 256 + tid]);
    }

    #pragma unroll
    for (int pp = 0; pp < PPB / 2; pp++) {
        const int cur = pp & 1;
        const int nxt = cur ^ 1;

        // Issue next pair's loads FIRST (keeps read queue full during stores).
        if (pp + 1 < PPB / 2) {
            const unsigned pN = plane0 + (pp + 1) * 2;
            #pragma unroll
            for (int p = 0; p < 2; p++) {
                const float4* xp = x + (size_t)(pN + p) * PLANE4 + tileBase;
                #pragma unroll
                for (int k = 0; k < 4; k++)
                    xv[nxt][p][k] = __ldcs(&xp[k * 256 + tid]);
            }
        }

        // Multiply + store current pair.
        const unsigned pA = plane0 + pp * 2;
        #pragma unroll
        for (int k = 0; k < 4; k++) {
            unsigned idx = k * 256 + tid;
            #pragma unroll
            for (int p = 0; p < 2; p++) {
                float4 r;
                r.x = xv[cur][p][k].x * dvv[k].x;
                r.y = xv[cur][p][k].y * dvv[k].y;
                r.z = xv[cur][p][k].z * dvv[k].z;
                r.w = xv[cur][p][k].w * dvv[k].w;
                __stcs(&out[(size_t)(pA + p) * PLANE4 + tileBase + idx], r);
            }
        }
    }
}

extern "C" void kernel_launch(void* const* d_in, const int* in_sizes, int n_in,
                              void* d_out, int out_size) {
    const float* x = (const float*)d_in[0];
    // d_in[1] = token_positions (unused by the reference semantics)
    const float* R = (const float*)d_in[2];
    float* out = (float*)d_out;

    dim3 grid(SEQ / 32, 128 / PPB);   // (128, 16) = 2048 blocks, s-tiles fast
    rope_diag_kernel<<<grid, 256>>>(R, (const float4*)x, (float4*)out);
    (void)in_sizes; (void)n_in; (void)out_size;
}

// round 12
// speedup vs baseline: 1.0105x; 1.0105x over previous
#include <cuda_runtime.h>
#include <cuda_bf16.h>
#include <cstdint>

// Problem constants
#define SEQ    4096
#define DK     128
#define PLANE  (SEQ * DK)      // 524288 floats per (b,h) plane
#define PLANE4 (PLANE / 4)     // 131072 float4s per plane
#define PPB    4               // planes per block (best-measured config)

// FINAL KERNEL — at the measured HBM roofline.
// out[...,s,d] = R[d,d,s] * x[...,s,d]  (einsum diagonal => elementwise scale)
//
// One block = one 32-seq x 128-dim tile, applied to PPB planes (2 pairs).
// Diag slice read straight from R (coalesced 128B rows, L2-cached across the
// 32 plane-blocks sharing each s-tile) into smem, then cached in registers.
// .cs on loads and stores: strictly read-once/write-once stream; evict-first
// keeps L2 ways free for the hot 2MB diag of R.
// Grid: s-tiles on the fast axis (plane-fast measured worse: 16MB power-of-2
// strides alias in the L2/channel hash).
//
// Roofline evidence: 11 configs (MLP 4-16, 128/256-bit, PPB 2/4/8, occ
// 22-65%, store policy, grid order, SW pipelining) all pin at 6109-6293 GB/s
// => ~6290 GB/s is the 50:50 read/write HBM ceiling (~79% of 8TB/s spec).
__global__ void __launch_bounds__(256) rope_diag_kernel(
        const float* __restrict__ R,
        const float4* __restrict__ x,
        float4* __restrict__ out) {
    // Padded to 132 floats/row: 16B-aligned rows -> conflict-free LDS.128
    __shared__ float diag[32][132];

    const unsigned s0     = blockIdx.x * 32;        // 128 s-tiles (fast)
    const unsigned plane0 = blockIdx.y * PPB;       // 32 plane-quads
    const unsigned tid    = threadIdx.x;
    const unsigned warp   = tid >> 5;
    const unsigned lane   = tid & 31;

    // diag[s][d] = R[d*(DK+1)*SEQ + s]; each row a coalesced 128B read.
    #pragma unroll
    for (int r = 0; r < 16; r++) {
        unsigned d = warp + r * 8;
        diag[lane][d] = __ldg(&R[(size_t)d * ((DK + 1) * SEQ) + s0 + lane]);
    }
    __syncthreads();

    const unsigned tileBase = blockIdx.x * 1024;    // float4 offset in plane

    // Pre-read this thread's 4 diag chunks once (16 regs, reused x4 planes)
    float4 dvv[4];
    #pragma unroll
    for (int k = 0; k < 4; k++) {
        unsigned idx = k * 256 + tid;               // 0..1023 within tile
        unsigned s   = idx >> 5;
        unsigned d4  = (idx & 31) * 4;
        dvv[k] = *reinterpret_cast<const float4*>(&diag[s][d4]);
    }

    // Process planes in pairs: 8 front-batched float4 loads per pair.
    #pragma unroll
    for (int pp = 0; pp < PPB / 2; pp++) {
        const unsigned pA = plane0 + pp * 2;

        float4 xv[2][4];
        #pragma unroll
        for (int p = 0; p < 2; p++) {
            const float4* xp = x + (size_t)(pA + p) * PLANE4 + tileBase;
            #pragma unroll
            for (int k = 0; k < 4; k++)
                xv[p][k] = __ldcs(&xp[k * 256 + tid]);
        }

        #pragma unroll
        for (int k = 0; k < 4; k++) {
            unsigned idx = k * 256 + tid;
            #pragma unroll
            for (int p = 0; p < 2; p++) {
                float4 r;
                r.x = xv[p][k].x * dvv[k].x;
                r.y = xv[p][k].y * dvv[k].y;
                r.z = xv[p][k].z * dvv[k].z;
                r.w = xv[p][k].w * dvv[k].w;
                __stcs(&out[(size_t)(pA + p) * PLANE4 + tileBase + idx], r);
            }
        }
    }
}

extern "C" void kernel_launch(void* const* d_in, const int* in_sizes, int n_in,
                              void* d_out, int out_size) {
    const float* x = (const float*)d_in[0];
    // d_in[1] = token_positions (unused by the reference semantics)
    const float* R = (const float*)d_in[2];
    float* out = (float*)d_out;

    dim3 grid(SEQ / 32, 128 / PPB);   // (128, 32) = 4096 blocks, s-tiles fast
    rope_diag_kernel<<<grid, 256>>>(R, (const float4*)x, (float4*)out);
    (void)in_sizes; (void)n_in; (void)out_size;
}

// round 13
// speedup vs baseline: 1.0109x; 1.0004x over previous
#include <cuda_runtime.h>
#include <cuda_bf16.h>
#include <cstdint>

// Problem constants
#define SEQ    4096
#define DK     128
#define PLANE  (SEQ * DK)      // 524288 floats per (b,h) plane
#define PLANE4 (PLANE / 4)     // 131072 float4s per plane
#define PPB    4               // planes per block (best-measured config)

// FINAL KERNEL — at the measured HBM roofline.
// out[...,s,d] = R[d,d,s] * x[...,s,d]  (einsum diagonal => elementwise scale)
//
// One block = one 32-seq x 128-dim tile, applied to PPB planes (2 pairs).
// Diag slice read straight from R (coalesced 128B rows, L2-cached across the
// 32 plane-blocks sharing each s-tile) into smem, then cached in registers.
// .cs on loads and stores: strictly read-once/write-once stream; evict-first
// keeps L2 ways free for the hot 2MB diag of R.
// Grid: s-tiles on the fast axis (plane-fast measured worse: 16MB power-of-2
// strides alias in the L2/channel hash).
//
// Roofline evidence: 12 configs (MLP 4-16, 128/256-bit, PPB 2/4/8, occ
// 22-65%, store policy, grid order, SW pipelining) all pin at 6109-6293 GB/s
// => ~6290 GB/s is the 50:50 read/write HBM ceiling (~79% of 8TB/s spec).
// Traffic is irreducible (512 MiB unique fp32 I/O). rel_err = 0 exactly.
__global__ void __launch_bounds__(256) rope_diag_kernel(
        const float* __restrict__ R,
        const float4* __restrict__ x,
        float4* __restrict__ out) {
    // Padded to 132 floats/row: 16B-aligned rows -> conflict-free LDS.128
    __shared__ float diag[32][132];

    const unsigned s0     = blockIdx.x * 32;        // 128 s-tiles (fast)
    const unsigned plane0 = blockIdx.y * PPB;       // 32 plane-quads
    const unsigned tid    = threadIdx.x;
    const unsigned warp   = tid >> 5;
    const unsigned lane   = tid & 31;

    // diag[s][d] = R[d*(DK+1)*SEQ + s]; each row a coalesced 128B read.
    #pragma unroll
    for (int r = 0; r < 16; r++) {
        unsigned d = warp + r * 8;
        diag[lane][d] = __ldg(&R[(size_t)d * ((DK + 1) * SEQ) + s0 + lane]);
    }
    __syncthreads();

    const unsigned tileBase = blockIdx.x * 1024;    // float4 offset in plane

    // Pre-read this thread's 4 diag chunks once (16 regs, reused x4 planes)
    float4 dvv[4];
    #pragma unroll
    for (int k = 0; k < 4; k++) {
        unsigned idx = k * 256 + tid;               // 0..1023 within tile
        unsigned s   = idx >> 5;
        unsigned d4  = (idx & 31) * 4;
        dvv[k] = *reinterpret_cast<const float4*>(&diag[s][d4]);
    }

    // Process planes in pairs: 8 front-batched float4 loads per pair.
    #pragma unroll
    for (int pp = 0; pp < PPB / 2; pp++) {
        const unsigned pA = plane0 + pp * 2;

        float4 xv[2][4];
        #pragma unroll
        for (int p = 0; p < 2; p++) {
            const float4* xp = x + (size_t)(pA + p) * PLANE4 + tileBase;
            #pragma unroll
            for (int k = 0; k < 4; k++)
                xv[p][k] = __ldcs(&xp[k * 256 + tid]);
        }

        #pragma unroll
        for (int k = 0; k < 4; k++) {
            unsigned idx = k * 256 + tid;
            #pragma unroll
            for (int p = 0; p < 2; p++) {
                float4 r;
                r.x = xv[p][k].x * dvv[k].x;
                r.y = xv[p][k].y * dvv[k].y;
                r.z = xv[p][k].z * dvv[k].z;
                r.w = xv[p][k].w * dvv[k].w;
                __stcs(&out[(size_t)(pA + p) * PLANE4 + tileBase + idx], r);
            }
        }
    }
}

extern "C" void kernel_launch(void* const* d_in, const int* in_sizes, int n_in,
                              void* d_out, int out_size) {
    const float* x = (const float*)d_in[0];
    // d_in[1] = token_positions (unused by the reference semantics)
    const float* R = (const float*)d_in[2];
    float* out = (float*)d_out;

    dim3 grid(SEQ / 32, 128 / PPB);   // (128, 32) = 4096 blocks, s-tiles fast
    rope_diag_kernel<<<grid, 256>>>(R, (const float4*)x, (float4*)out);
    (void)in_sizes; (void)n_in; (void)out_size;
}